// round 1
// baseline (speedup 1.0000x reference)
#include <cuda_runtime.h>
#include <math.h>

#define T_DIM 2048
#define C_DIM 8
#define S_DIM 16
#define N_DIM 10000
#define NT 128
#define TT 32

// ---------------- scratch (static __device__ allowed) ----------------
__device__ float g_E[C_DIM * S_DIM * N_DIM];     // normalized emission probs, [c][s][n]
__device__ float g_H[T_DIM * C_DIM * S_DIM];     // hidden probs, [t][c][s]
__device__ float g_cw[T_DIM * C_DIM];            // chain weights, [t][c]
__device__ float g_pow[11 * C_DIM * S_DIM * S_DIM]; // A^(2^k), [k][c][i][j]
__device__ float g_H0[C_DIM * S_DIM];            // initial distribution

// ---------------- f32x2 helpers ----------------
typedef unsigned long long u64;
__device__ __forceinline__ u64 pack2(float x, float y) {
    u64 r; asm("mov.b64 %0, {%1,%2};" : "=l"(r) : "f"(x), "f"(y)); return r;
}
__device__ __forceinline__ float2 unpack2(u64 v) {
    float2 r; asm("mov.b64 {%0,%1}, %2;" : "=f"(r.x), "=f"(r.y) : "l"(v)); return r;
}
__device__ __forceinline__ u64 fma2(u64 a, u64 b, u64 c) {
    u64 d; asm("fma.rn.f32x2 %0, %1, %2, %3;" : "=l"(d) : "l"(a), "l"(b), "l"(c)); return d;
}

// ---------------- kernel 1: transition softmax + matrix powers + h0 ----------------
__global__ void k_prep_small(const float* __restrict__ init_logits,
                             const float* __restrict__ tr_logits) {
    int tid = threadIdx.x;
    if (tid < 128) {
        // softmax row (c,i) of transition -> g_pow[0]
        const float* row = tr_logits + tid * 16;
        float x[16]; float m = -1e30f;
        #pragma unroll
        for (int j = 0; j < 16; j++) { x[j] = row[j]; m = fmaxf(m, x[j]); }
        float s = 0.f;
        #pragma unroll
        for (int j = 0; j < 16; j++) { x[j] = __expf(x[j] - m); s += x[j]; }
        float inv = 1.0f / s;
        #pragma unroll
        for (int j = 0; j < 16; j++) g_pow[tid * 16 + j] = x[j] * inv;
    } else if (tid < 136) {
        // h0: softmax row c of state_init
        int c = tid - 128;
        const float* row = init_logits + c * 16;
        float x[16]; float m = -1e30f;
        #pragma unroll
        for (int j = 0; j < 16; j++) { x[j] = row[j]; m = fmaxf(m, x[j]); }
        float s = 0.f;
        #pragma unroll
        for (int j = 0; j < 16; j++) { x[j] = __expf(x[j] - m); s += x[j]; }
        float inv = 1.0f / s;
        #pragma unroll
        for (int j = 0; j < 16; j++) g_H0[c * 16 + j] = x[j] * inv;
    }
    __syncthreads();
    // repeated squaring: g_pow[k] = g_pow[k-1]^2
    for (int k = 1; k < 11; k++) {
        for (int e = tid; e < C_DIM * 256; e += blockDim.x) {
            int c = e >> 8, ij = e & 255, i = ij >> 4, j = ij & 15;
            const float* P = g_pow + (k - 1) * C_DIM * 256 + c * 256;
            float s = 0.f;
            #pragma unroll
            for (int m2 = 0; m2 < 16; m2++) s += P[i * 16 + m2] * P[m2 * 16 + j];
            g_pow[k * C_DIM * 256 + c * 256 + ij] = s;
        }
        __syncthreads();
    }
}

// ---------------- kernel 2: chain-weight softmax ----------------
__global__ void k_cw(const float* __restrict__ cw_logits) {
    int t = blockIdx.x * blockDim.x + threadIdx.x;
    if (t >= T_DIM) return;
    float x[8]; float m = -1e30f;
    #pragma unroll
    for (int c = 0; c < 8; c++) { x[c] = cw_logits[t * 8 + c]; m = fmaxf(m, x[c]); }
    float s = 0.f;
    #pragma unroll
    for (int c = 0; c < 8; c++) { x[c] = __expf(x[c] - m); s += x[c]; }
    float inv = 1.0f / s;
    #pragma unroll
    for (int c = 0; c < 8; c++) g_cw[t * 8 + c] = x[c] * inv;
}

// ---------------- kernel 3: emission softmax over N ----------------
__global__ void k_emis(const float* __restrict__ em_logits) {
    __shared__ float red[256];
    int row = blockIdx.x;  // (c*16+s)
    int tid = threadIdx.x;
    const float* src = em_logits + (size_t)row * N_DIM;
    float m = -1e30f;
    for (int n = tid; n < N_DIM; n += 256) m = fmaxf(m, src[n]);
    red[tid] = m; __syncthreads();
    for (int o = 128; o; o >>= 1) { if (tid < o) red[tid] = fmaxf(red[tid], red[tid + o]); __syncthreads(); }
    m = red[0]; __syncthreads();
    float s = 0.f;
    for (int n = tid; n < N_DIM; n += 256) s += __expf(src[n] - m);
    red[tid] = s; __syncthreads();
    for (int o = 128; o; o >>= 1) { if (tid < o) red[tid] += red[tid + o]; __syncthreads(); }
    float lse = m + __logf(red[0]);
    float* dst = g_E + (size_t)row * N_DIM;
    for (int n = tid; n < N_DIM; n += 256) dst[n] = __expf(src[n] - lse);
}

// ---------------- kernel 4: hidden states via A^t binary decomposition ----------------
__global__ void k_H(float* __restrict__ out_hidden) {
    int tid = threadIdx.x;
    int t = blockIdx.x * 32 + (tid >> 3);
    int c = tid & 7;
    float h[16];
    #pragma unroll
    for (int s = 0; s < 16; s++) h[s] = g_H0[c * 16 + s];
    for (int k = 0; k < 11; k++) {
        if ((t >> k) & 1) {
            const float* P = g_pow + k * C_DIM * 256 + c * 256;
            float nh[16];
            #pragma unroll
            for (int j = 0; j < 16; j++) {
                float s0 = 0.f;
                #pragma unroll
                for (int i = 0; i < 16; i++) s0 += h[i] * P[i * 16 + j];
                nh[j] = s0;
            }
            #pragma unroll
            for (int j = 0; j < 16; j++) h[j] = nh[j];
        }
    }
    int base = (t * 8 + c) * 16;
    #pragma unroll
    for (int s = 0; s < 16; s++) {
        g_H[base + s] = h[s];
        if (out_hidden) out_hidden[base + s] = __logf(h[s]);
    }
}

// ---------------- kernel 5: main emission GEMM + log + chain mix ----------------
__global__ void __launch_bounds__(256, 2)
k_main(float* __restrict__ out_obs, float* __restrict__ out_obs_c) {
    extern __shared__ float smem[];
    float* Es  = smem;                  // [128 rows][128 n] = 16384 floats
    float* Hs  = smem + 16384;          // [32 t][8 c][16 s] = 4096 floats
    float* CWs = smem + 16384 + 4096;   // [32 t][8 c] = 256 floats
    int tid = threadIdx.x;
    int n0 = blockIdx.x * NT;
    int t0 = blockIdx.y * TT;

    // load E tile (zero-fill OOB n)
    float4* Es4 = (float4*)Es;
    for (int idx = tid; idx < 128 * 32; idx += 256) {
        int r = idx >> 5, q = idx & 31;
        int n = n0 + q * 4;
        float4 v;
        if (n < N_DIM) v = *(const float4*)(g_E + (size_t)r * N_DIM + n);
        else v = make_float4(0.f, 0.f, 0.f, 0.f);
        Es4[idx] = v;
    }
    // load H tile
    {
        const float4* src = (const float4*)(g_H + t0 * 128);
        float4* dst = (float4*)Hs;
        for (int idx = tid; idx < 1024; idx += 256) dst[idx] = src[idx];
    }
    CWs[tid] = g_cw[t0 * 8 + tid];
    __syncthreads();

    int nq = tid & 31;       // which n-quad
    int tg = tid >> 5;       // which t-group (4 t each)
    int tl0 = tg * 4;
    int nvalid = (n0 + nq * 4) < N_DIM;

    u64 wsum[4][2];
    #pragma unroll
    for (int a = 0; a < 4; a++) { wsum[a][0] = 0ULL; wsum[a][1] = 0ULL; }

    const ulonglong2* Es2 = (const ulonglong2*)Es;

    #pragma unroll 1
    for (int c = 0; c < 8; c++) {
        u64 acc[4][2];
        #pragma unroll
        for (int a = 0; a < 4; a++) { acc[a][0] = 0ULL; acc[a][1] = 0ULL; }
        #pragma unroll
        for (int sq = 0; sq < 4; sq++) {
            float4 hv[4];
            #pragma unroll
            for (int tt = 0; tt < 4; tt++)
                hv[tt] = *(const float4*)(Hs + (tl0 + tt) * 128 + c * 16 + sq * 4);
            #pragma unroll
            for (int si = 0; si < 4; si++) {
                ulonglong2 ev = Es2[(c * 16 + sq * 4 + si) * 32 + nq];
                #pragma unroll
                for (int tt = 0; tt < 4; tt++) {
                    float hsc = ((const float*)&hv[tt])[si];
                    u64 hh = pack2(hsc, hsc);
                    acc[tt][0] = fma2(hh, ev.x, acc[tt][0]);
                    acc[tt][1] = fma2(hh, ev.y, acc[tt][1]);
                }
            }
        }
        // per-c epilogue: weight-accumulate + store log_obs_
        #pragma unroll
        for (int tt = 0; tt < 4; tt++) {
            float cw = CWs[(tl0 + tt) * 8 + c];
            u64 cwp = pack2(cw, cw);
            wsum[tt][0] = fma2(cwp, acc[tt][0], wsum[tt][0]);
            wsum[tt][1] = fma2(cwp, acc[tt][1], wsum[tt][1]);
            if (out_obs_c && nvalid) {
                float2 p0 = unpack2(acc[tt][0]);
                float2 p1 = unpack2(acc[tt][1]);
                float4 o = make_float4(__logf(p0.x), __logf(p0.y), __logf(p1.x), __logf(p1.y));
                int t = t0 + tl0 + tt;
                *(float4*)(out_obs_c + (size_t)(t * 8 + c) * N_DIM + n0 + nq * 4) = o;
            }
        }
    }
    // store log_obs
    #pragma unroll
    for (int tt = 0; tt < 4; tt++) {
        if (nvalid) {
            float2 p0 = unpack2(wsum[tt][0]);
            float2 p1 = unpack2(wsum[tt][1]);
            float4 o = make_float4(__logf(p0.x), __logf(p0.y), __logf(p1.x), __logf(p1.y));
            int t = t0 + tl0 + tt;
            *(float4*)(out_obs + (size_t)t * N_DIM + n0 + nq * 4) = o;
        }
    }
}

// ---------------- launch ----------------
extern "C" void kernel_launch(void* const* d_in, const int* in_sizes, int n_in,
                              void* d_out, int out_size) {
    const float* cw_logits   = (const float*)d_in[0];  // (T, C)
    const float* init_logits = (const float*)d_in[1];  // (C, S)
    const float* em_logits   = (const float*)d_in[2];  // (C, S, N)
    const float* tr_logits   = (const float*)d_in[3];  // (C, S, S)
    float* out = (float*)d_out;

    const long long s0 = (long long)T_DIM * N_DIM;                 // log_obs
    const long long s1 = (long long)T_DIM * C_DIM * N_DIM;         // log_obs_
    const long long s2 = (long long)T_DIM * C_DIM * S_DIM;         // log_hidden
    long long osz = (long long)out_size;

    float* out_obs    = out;
    float* out_obs_c  = (osz >= s0 + s1)      ? out + s0      : nullptr;
    float* out_hidden = (osz >= s0 + s1 + s2) ? out + s0 + s1 : nullptr;

    const int smem_bytes = (16384 + 4096 + 256) * 4;  // 82944
    cudaFuncSetAttribute(k_main, cudaFuncAttributeMaxDynamicSharedMemorySize, smem_bytes);

    k_prep_small<<<1, 256>>>(init_logits, tr_logits);
    k_cw<<<8, 256>>>(cw_logits);
    k_emis<<<C_DIM * S_DIM, 256>>>(em_logits);
    k_H<<<T_DIM / 32, 256>>>(out_hidden);

    dim3 grid((N_DIM + NT - 1) / NT, T_DIM / TT);
    k_main<<<grid, 256, smem_bytes>>>(out_obs, out_obs_c);
}

// round 2
// speedup vs baseline: 1.2922x; 1.2922x over previous
#include <cuda_runtime.h>
#include <math.h>

#define T_DIM 2048
#define C_DIM 8
#define S_DIM 16
#define N_DIM 10000
#define NT 128
#define TT 64

// ---------------- scratch ----------------
__device__ float g_E[C_DIM * S_DIM * N_DIM];        // emission probs [c][s][n]
__device__ float g_H[T_DIM * C_DIM * S_DIM];        // hidden probs [t][c][s]
__device__ float g_cw[T_DIM * C_DIM];               // chain weights [t][c]
__device__ float g_pow[11 * C_DIM * S_DIM * S_DIM]; // A^(2^k) [k][c][i][j]
__device__ float g_H0[C_DIM * S_DIM];

// ---------------- f32x2 helpers ----------------
typedef unsigned long long u64;
__device__ __forceinline__ u64 pack2(float x, float y) {
    u64 r; asm("mov.b64 %0, {%1,%2};" : "=l"(r) : "f"(x), "f"(y)); return r;
}
__device__ __forceinline__ float2 unpack2(u64 v) {
    float2 r; asm("mov.b64 {%0,%1}, %2;" : "=f"(r.x), "=f"(r.y) : "l"(v)); return r;
}
__device__ __forceinline__ u64 fma2(u64 a, u64 b, u64 c) {
    u64 d; asm("fma.rn.f32x2 %0, %1, %2, %3;" : "=l"(d) : "l"(a), "l"(b), "l"(c)); return d;
}

#define POW_FLOATS (11 * C_DIM * 256)   // 22528 floats = 90112 B

// ---------------- kernel 1: softmax(trans) + matrix powers (all in smem) ----------------
__global__ void k_prep_small(const float* __restrict__ init_logits,
                             const float* __restrict__ tr_logits) {
    extern __shared__ float Ps[];   // [11][C][16][16]
    int tid = threadIdx.x;
    if (tid < 128) {
        const float* row = tr_logits + tid * 16;
        float x[16]; float m = -1e30f;
        #pragma unroll
        for (int j = 0; j < 16; j++) { x[j] = row[j]; m = fmaxf(m, x[j]); }
        float s = 0.f;
        #pragma unroll
        for (int j = 0; j < 16; j++) { x[j] = __expf(x[j] - m); s += x[j]; }
        float inv = 1.0f / s;
        #pragma unroll
        for (int j = 0; j < 16; j++) Ps[tid * 16 + j] = x[j] * inv;
    } else if (tid < 136) {
        int c = tid - 128;
        const float* row = init_logits + c * 16;
        float x[16]; float m = -1e30f;
        #pragma unroll
        for (int j = 0; j < 16; j++) { x[j] = row[j]; m = fmaxf(m, x[j]); }
        float s = 0.f;
        #pragma unroll
        for (int j = 0; j < 16; j++) { x[j] = __expf(x[j] - m); s += x[j]; }
        float inv = 1.0f / s;
        #pragma unroll
        for (int j = 0; j < 16; j++) g_H0[c * 16 + j] = x[j] * inv;
    }
    __syncthreads();
    for (int k = 1; k < 11; k++) {
        for (int e = tid; e < C_DIM * 256; e += 256) {
            int c = e >> 8, ij = e & 255, i = ij >> 4, j = ij & 15;
            const float* P = Ps + (k - 1) * C_DIM * 256 + c * 256;
            float s = 0.f;
            #pragma unroll
            for (int m2 = 0; m2 < 16; m2++) s += P[i * 16 + m2] * P[m2 * 16 + j];
            Ps[k * C_DIM * 256 + c * 256 + ij] = s;
        }
        __syncthreads();
    }
    // dump all powers to global
    float4* dst = (float4*)g_pow;
    const float4* src = (const float4*)Ps;
    for (int idx = tid; idx < POW_FLOATS / 4; idx += 256) dst[idx] = src[idx];
}

// ---------------- kernel 2: chain-weight softmax ----------------
__global__ void k_cw(const float* __restrict__ cw_logits) {
    int t = blockIdx.x * blockDim.x + threadIdx.x;
    if (t >= T_DIM) return;
    float x[8]; float m = -1e30f;
    #pragma unroll
    for (int c = 0; c < 8; c++) { x[c] = cw_logits[t * 8 + c]; m = fmaxf(m, x[c]); }
    float s = 0.f;
    #pragma unroll
    for (int c = 0; c < 8; c++) { x[c] = __expf(x[c] - m); s += x[c]; }
    float inv = 1.0f / s;
    #pragma unroll
    for (int c = 0; c < 8; c++) g_cw[t * 8 + c] = x[c] * inv;
}

// ---------------- kernel 3: emission softmax over N ----------------
__global__ void k_emis(const float* __restrict__ em_logits) {
    __shared__ float red[256];
    int row = blockIdx.x;  // (c*16+s)
    int tid = threadIdx.x;
    const float* src = em_logits + (size_t)row * N_DIM;
    float m = -1e30f;
    for (int n = tid; n < N_DIM; n += 256) m = fmaxf(m, src[n]);
    red[tid] = m; __syncthreads();
    for (int o = 128; o; o >>= 1) { if (tid < o) red[tid] = fmaxf(red[tid], red[tid + o]); __syncthreads(); }
    m = red[0]; __syncthreads();
    float s = 0.f;
    for (int n = tid; n < N_DIM; n += 256) s += __expf(src[n] - m);
    red[tid] = s; __syncthreads();
    for (int o = 128; o; o >>= 1) { if (tid < o) red[tid] += red[tid + o]; __syncthreads(); }
    float lse = m + __logf(red[0]);
    float* dst = g_E + (size_t)row * N_DIM;
    for (int n = tid; n < N_DIM; n += 256) dst[n] = __expf(src[n] - lse);
}

// ---------------- kernel 4: hidden states, warp-cooperative binary decomposition ----------------
// Block: 256 threads = 8 warps; handles 16 t values. Warp task = (t, chain-pair).
// Lanes 0-15 -> chain 2p, lanes 16-31 -> chain 2p+1. Lane holds h[s], s = lane&15.
// Whole warp shares one t -> uniform branch on bits of t.
__global__ void __launch_bounds__(256) k_H(float* __restrict__ out_hidden) {
    extern __shared__ float Ps[];   // staged g_pow, 90112 B
    int tid = threadIdx.x;
    {
        float4* dst = (float4*)Ps;
        const float4* src = (const float4*)g_pow;
        for (int idx = tid; idx < POW_FLOATS / 4; idx += 256) dst[idx] = src[idx];
    }
    __syncthreads();

    int w = tid >> 5;
    int lane = tid & 31;
    int s = lane & 15;
    int t0 = blockIdx.x * 16;

    #pragma unroll 1
    for (int iter = 0; iter < 8; iter++) {
        int task = w + iter * 8;          // 0..63
        int t = t0 + (task >> 2);         // uniform across warp
        int p = task & 3;
        int c = 2 * p + (lane >> 4);

        float h = g_H0[c * 16 + s];
        #pragma unroll
        for (int k = 0; k < 11; k++) {
            if ((t >> k) & 1) {
                const float* P = Ps + (k * 8 + c) * 256;
                float pcol[16];
                #pragma unroll
                for (int i = 0; i < 16; i++) pcol[i] = P[i * 16 + s];
                float nh = 0.f;
                #pragma unroll
                for (int i = 0; i < 16; i++)
                    nh = fmaf(__shfl_sync(0xffffffffu, h, i, 16), pcol[i], nh);
                h = nh;
            }
        }
        int idx = (t * 8 + c) * 16 + s;
        g_H[idx] = h;
        if (out_hidden) out_hidden[idx] = __logf(h);
    }
}

// ---------------- kernel 5: main emission GEMM + log + chain mix ----------------
// Block 256 thr: nq = tid&31 (n-quad of 4), tg = tid>>5 (8 groups x 8 t each).
// Tile: 128 n x 64 t. E vector reused across 8 t -> halved smem phases vs tt=4.
__global__ void __launch_bounds__(256, 2)
k_main(float* __restrict__ out_obs, float* __restrict__ out_obs_c) {
    extern __shared__ float smem[];
    float* Es  = smem;                    // [128 rows][128 n] = 16384 floats (64KB)
    float* Hs  = smem + 16384;            // [64 t][8 c][16 s] = 8192 floats (32KB)
    float* CWs = smem + 16384 + 8192;     // [64 t][8 c] = 512 floats (2KB)
    int tid = threadIdx.x;
    int n0 = blockIdx.x * NT;
    int t0 = blockIdx.y * TT;

    // load E tile (zero-fill OOB n)
    float4* Es4 = (float4*)Es;
    for (int idx = tid; idx < 128 * 32; idx += 256) {
        int r = idx >> 5, q = idx & 31;
        int n = n0 + q * 4;
        float4 v;
        if (n < N_DIM) v = *(const float4*)(g_E + (size_t)r * N_DIM + n);
        else v = make_float4(0.f, 0.f, 0.f, 0.f);
        Es4[idx] = v;
    }
    // load H tile (64 t x 128)
    {
        const float4* src = (const float4*)(g_H + t0 * 128);
        float4* dst = (float4*)Hs;
        for (int idx = tid; idx < 2048; idx += 256) dst[idx] = src[idx];
    }
    for (int idx = tid; idx < 512; idx += 256) CWs[idx] = g_cw[t0 * 8 + idx];
    __syncthreads();

    int nq = tid & 31;        // n-quad
    int tg = tid >> 5;        // t-group (8 t each)
    int tl0 = tg * 8;
    int nvalid = (n0 + nq * 4) < N_DIM;

    u64 wsum[8][2];
    #pragma unroll
    for (int a = 0; a < 8; a++) { wsum[a][0] = 0ULL; wsum[a][1] = 0ULL; }

    const ulonglong2* Es2 = (const ulonglong2*)Es;

    #pragma unroll 1
    for (int c = 0; c < 8; c++) {
        u64 acc[8][2];
        #pragma unroll
        for (int a = 0; a < 8; a++) { acc[a][0] = 0ULL; acc[a][1] = 0ULL; }
        #pragma unroll
        for (int sq = 0; sq < 4; sq++) {
            ulonglong2 ev[4];
            #pragma unroll
            for (int si = 0; si < 4; si++)
                ev[si] = Es2[(c * 16 + sq * 4 + si) * 32 + nq];
            #pragma unroll
            for (int tt = 0; tt < 8; tt++) {
                float4 hv = *(const float4*)(Hs + (tl0 + tt) * 128 + c * 16 + sq * 4);
                #pragma unroll
                for (int si = 0; si < 4; si++) {
                    float hsc = ((const float*)&hv)[si];
                    u64 hh = pack2(hsc, hsc);
                    acc[tt][0] = fma2(hh, ev[si].x, acc[tt][0]);
                    acc[tt][1] = fma2(hh, ev[si].y, acc[tt][1]);
                }
            }
        }
        // per-c epilogue: weight-accumulate + store log_obs_
        #pragma unroll
        for (int tt = 0; tt < 8; tt++) {
            float cw = CWs[(tl0 + tt) * 8 + c];
            u64 cwp = pack2(cw, cw);
            wsum[tt][0] = fma2(cwp, acc[tt][0], wsum[tt][0]);
            wsum[tt][1] = fma2(cwp, acc[tt][1], wsum[tt][1]);
            if (out_obs_c && nvalid) {
                float2 p0 = unpack2(acc[tt][0]);
                float2 p1 = unpack2(acc[tt][1]);
                float4 o = make_float4(__logf(p0.x), __logf(p0.y), __logf(p1.x), __logf(p1.y));
                int t = t0 + tl0 + tt;
                *(float4*)(out_obs_c + (size_t)(t * 8 + c) * N_DIM + n0 + nq * 4) = o;
            }
        }
    }
    // store log_obs
    #pragma unroll
    for (int tt = 0; tt < 8; tt++) {
        if (nvalid) {
            float2 p0 = unpack2(wsum[tt][0]);
            float2 p1 = unpack2(wsum[tt][1]);
            float4 o = make_float4(__logf(p0.x), __logf(p0.y), __logf(p1.x), __logf(p1.y));
            int t = t0 + tl0 + tt;
            *(float4*)(out_obs + (size_t)t * N_DIM + n0 + nq * 4) = o;
        }
    }
}

// ---------------- launch ----------------
extern "C" void kernel_launch(void* const* d_in, const int* in_sizes, int n_in,
                              void* d_out, int out_size) {
    const float* cw_logits   = (const float*)d_in[0];  // (T, C)
    const float* init_logits = (const float*)d_in[1];  // (C, S)
    const float* em_logits   = (const float*)d_in[2];  // (C, S, N)
    const float* tr_logits   = (const float*)d_in[3];  // (C, S, S)
    float* out = (float*)d_out;

    const long long s0 = (long long)T_DIM * N_DIM;
    const long long s1 = (long long)T_DIM * C_DIM * N_DIM;
    const long long s2 = (long long)T_DIM * C_DIM * S_DIM;
    long long osz = (long long)out_size;

    float* out_obs    = out;
    float* out_obs_c  = (osz >= s0 + s1)      ? out + s0      : nullptr;
    float* out_hidden = (osz >= s0 + s1 + s2) ? out + s0 + s1 : nullptr;

    const int pow_smem  = POW_FLOATS * 4;               // 90112
    const int main_smem = (16384 + 8192 + 512) * 4;     // 100352
    cudaFuncSetAttribute(k_prep_small, cudaFuncAttributeMaxDynamicSharedMemorySize, pow_smem);
    cudaFuncSetAttribute(k_H,          cudaFuncAttributeMaxDynamicSharedMemorySize, pow_smem);
    cudaFuncSetAttribute(k_main,       cudaFuncAttributeMaxDynamicSharedMemorySize, main_smem);

    k_prep_small<<<1, 256, pow_smem>>>(init_logits, tr_logits);
    k_cw<<<8, 256>>>(cw_logits);
    k_emis<<<C_DIM * S_DIM, 256>>>(em_logits);
    k_H<<<T_DIM / 16, 256, pow_smem>>>(out_hidden);

    dim3 grid((N_DIM + NT - 1) / NT, T_DIM / TT);
    k_main<<<grid, 256, main_smem>>>(out_obs, out_obs_c);
}